// round 6
// baseline (speedup 1.0000x reference)
#include <cuda_runtime.h>
#include <cstdint>
#include <cstddef>

#define NN 50000
#define EE 800000
#define HID 128
#define EDIM 32
#define XS2 132        // duplicated-X stride for 64-row tiles (2*64+4 pad)
#define NB_SCAN 196    // ceil(NN/256)

// ---------------- scratch (static __device__ — allocation-free) ----------------
__device__ __align__(16) float g_x0[(size_t)NN * HID];
__device__ __align__(16) float g_x1[(size_t)NN * HID];
__device__ __align__(16) float g_mx[(size_t)NN * HID];
__device__ __align__(16) float g_me[(size_t)NN * HID];
__device__ __align__(16) float g_scores[NN];
__device__ int g_src[EE];
__device__ int g_dst[EE];
__device__ int g_csr_src[EE];
__device__ int g_cnt[NN];
__device__ int g_rowptr[NN];
__device__ int g_cur[NN];
__device__ int g_partial[256];
__device__ unsigned g_maxbits;
__device__ float g_sum;

// ---------------- helpers ----------------
__device__ __forceinline__ void red_add_v4(float* addr, float4 v) {
    asm volatile("red.global.add.v4.f32 [%0], {%1,%2,%3,%4};"
                 :: "l"(addr), "f"(v.x), "f"(v.y), "f"(v.z), "f"(v.w)
                 : "memory");
}
// packed f32x2 FMA: d = a*b + c (two fp32 lanes per instruction)
__device__ __forceinline__ unsigned long long fma2(unsigned long long a,
                                                   unsigned long long b,
                                                   unsigned long long c) {
    unsigned long long d;
    asm("fma.rn.f32x2 %0, %1, %2, %3;" : "=l"(d) : "l"(a), "l"(b), "l"(c));
    return d;
}
__device__ __forceinline__ void unpack2(unsigned long long v, float& lo, float& hi) {
    asm("mov.b64 {%0, %1}, %2;" : "=f"(lo), "=f"(hi) : "l"(v));
}
__device__ __forceinline__ void sts_dup(float* p, float v) {
    *(float2*)p = make_float2(v, v);
}
__device__ __forceinline__ unsigned enc_ordered(float f) {
    unsigned b = __float_as_uint(f);
    return (b & 0x80000000u) ? ~b : (b | 0x80000000u);
}
__device__ __forceinline__ float dec_ordered(unsigned u) {
    unsigned b = (u & 0x80000000u) ? (u ^ 0x80000000u) : ~u;
    return __uint_as_float(b);
}

// ---------------- edge index normalization + cnt zeroing ----------------
__global__ void convert_edges(const void* __restrict__ ei) {
    __shared__ int is64;
    if (threadIdx.x == 0) {
        const int* p = (const int*)ei;
        int z = 0;
        #pragma unroll
        for (int i = 0; i < 64; i++) z |= p[2 * i + 1];
        is64 = (z == 0);
    }
    __syncthreads();
    const int idx = blockIdx.x * blockDim.x + threadIdx.x;
    const int stride = gridDim.x * blockDim.x;
    for (int i = idx; i < NN; i += stride) g_cnt[i] = 0;
    if (is64) {
        const long long* p = (const long long*)ei;
        for (int e = idx; e < EE; e += stride) {
            g_src[e] = (int)p[e];
            g_dst[e] = (int)p[EE + e];
        }
    } else {
        const int* p = (const int*)ei;
        for (int e = idx; e < EE; e += stride) {
            g_src[e] = p[e];
            g_dst[e] = p[EE + e];
        }
    }
}

// ---------------- CSR build ----------------
__global__ void hist_kernel() {
    const int idx = blockIdx.x * blockDim.x + threadIdx.x;
    const int stride = gridDim.x * blockDim.x;
    for (int e = idx; e < EE; e += stride) atomicAdd(&g_cnt[g_dst[e]], 1);
}

__global__ void scan_reduce() {
    __shared__ int sh[256];
    const int t = threadIdx.x;
    const int i = blockIdx.x * 256 + t;
    sh[t] = (i < NN) ? g_cnt[i] : 0;
    __syncthreads();
    #pragma unroll
    for (int o = 128; o; o >>= 1) {
        if (t < o) sh[t] += sh[t + o];
        __syncthreads();
    }
    if (t == 0) g_partial[blockIdx.x] = sh[0];
}

__global__ void scan_partials() {
    __shared__ int sh[256];
    const int t = threadIdx.x;
    const int v = (t < NB_SCAN) ? g_partial[t] : 0;
    sh[t] = v;
    __syncthreads();
    #pragma unroll
    for (int off = 1; off < 256; off <<= 1) {
        int a = (t >= off) ? sh[t - off] : 0;
        __syncthreads();
        sh[t] += a;
        __syncthreads();
    }
    g_partial[t] = sh[t] - v;   // exclusive
}

__global__ void scan_final() {
    __shared__ int sh[256];
    const int t = threadIdx.x;
    const int i = blockIdx.x * 256 + t;
    const int v = (i < NN) ? g_cnt[i] : 0;
    sh[t] = v;
    __syncthreads();
    #pragma unroll
    for (int off = 1; off < 256; off <<= 1) {
        int a = (t >= off) ? sh[t - off] : 0;
        __syncthreads();
        sh[t] += a;
        __syncthreads();
    }
    if (i < NN) {
        const int excl = sh[t] - v + g_partial[blockIdx.x];
        g_rowptr[i] = excl;
        g_cur[i] = excl;
    }
}

__global__ void fill_kernel() {
    const int idx = blockIdx.x * blockDim.x + threadIdx.x;
    const int stride = gridDim.x * blockDim.x;
    for (int e = idx; e < EE; e += stride) {
        const int d = g_dst[e];
        const int p = atomicAdd(&g_cur[d], 1);
        g_csr_src[p] = g_src[e];
    }
}

// ---------------- zero m_e + scalars ----------------
__global__ void zero_me() {
    const int n4 = NN * HID / 4;
    float4* a = (float4*)g_me;
    const float4 z = make_float4(0.f, 0.f, 0.f, 0.f);
    for (int i = blockIdx.x * blockDim.x + threadIdx.x; i < n4;
         i += gridDim.x * blockDim.x)
        a[i] = z;
    if (blockIdx.x == 0 && threadIdx.x == 0) { g_maxbits = 0u; g_sum = 0.f; }
}

// ---------------- f32x2 projection GEMM: out = relu(in @ W + b) ----------------
// Block = 512 threads = 16 warps. Tile = 64 rows x 128 cols.
// Warp: rg = w&7 -> rows [rg*8,+8); cg = w>>3 -> cols [cg*64,+64); lane -> 2 cols.
// X staged DUPLICATED (X_s[k*XS2 + 2r] = X_s[.. +2r+1] = x[r][k]) so the FMA2
// x-operand comes straight from a broadcast LDS.128; W col-pair comes straight
// from LDS.64. Per warp-k: 1 LDS.64 + 4 LDS.128 + 8 FMA2, zero MOVs.
// W staged in 128-k chunks (2 phases for K=256).
template <int K, bool CONCAT>
__global__ void proj_kernel(const float* __restrict__ in0,
                            const float* __restrict__ in1,
                            const float* __restrict__ W,
                            const float* __restrict__ bias,
                            float* __restrict__ out, int rows) {
    extern __shared__ float sh[];
    float* W_s = sh;               // 128*128 floats (one K-chunk)
    float* X_s = sh + 128 * 128;   // K*XS2 floats (duplicated)
    const int tid = threadIdx.x;
    const int tile0 = blockIdx.x * 64;

    {   // stage X duplicated
        const int KC = K / 4;
        for (int i = tid; i < 64 * KC; i += 512) {
            const int r = i & 63, kc = i >> 6;
            const int g = tile0 + r;
            float4 v = make_float4(0.f, 0.f, 0.f, 0.f);
            if (g < rows) {
                if (CONCAT) {
                    v = (kc < 32) ? ((const float4*)(in0 + (size_t)g * 128))[kc]
                                  : ((const float4*)(in1 + (size_t)g * 128))[kc - 32];
                } else {
                    v = ((const float4*)(in0 + (size_t)g * K))[kc];
                }
            }
            float* xp = &X_s[(kc * 4) * XS2 + 2 * r];
            sts_dup(xp + 0 * XS2, v.x);
            sts_dup(xp + 1 * XS2, v.y);
            sts_dup(xp + 2 * XS2, v.z);
            sts_dup(xp + 3 * XS2, v.w);
        }
    }

    const int lane = tid & 31;
    const int w = tid >> 5;
    const int rg = w & 7, cg = w >> 3;
    const int rb = rg * 8;
    const unsigned long long bp =
        ((const unsigned long long*)bias)[cg * 32 + lane];
    unsigned long long acc[8];
    #pragma unroll
    for (int p = 0; p < 8; p++) acc[p] = bp;

    #pragma unroll
    for (int ph = 0; ph < K / 128; ph++) {
        __syncthreads();
        {   // stage W chunk
            const float4* Wg = (const float4*)(W + (size_t)ph * 128 * 128);
            float4* Ws4 = (float4*)W_s;
            for (int i = tid; i < 128 * 32; i += 512) Ws4[i] = Wg[i];
        }
        __syncthreads();

        const float* Xph = X_s + (size_t)ph * 128 * XS2;
        #pragma unroll 4
        for (int k = 0; k < 128; k++) {
            const unsigned long long wp =
                *(const unsigned long long*)&W_s[k * 128 + cg * 64 + lane * 2];
            const float* xb = &Xph[k * XS2 + 2 * rb];
            const ulonglong2 x01 = *(const ulonglong2*)(xb + 0);
            const ulonglong2 x23 = *(const ulonglong2*)(xb + 4);
            const ulonglong2 x45 = *(const ulonglong2*)(xb + 8);
            const ulonglong2 x67 = *(const ulonglong2*)(xb + 12);
            acc[0] = fma2(x01.x, wp, acc[0]);
            acc[1] = fma2(x01.y, wp, acc[1]);
            acc[2] = fma2(x23.x, wp, acc[2]);
            acc[3] = fma2(x23.y, wp, acc[3]);
            acc[4] = fma2(x45.x, wp, acc[4]);
            acc[5] = fma2(x45.y, wp, acc[5]);
            acc[6] = fma2(x67.x, wp, acc[6]);
            acc[7] = fma2(x67.y, wp, acc[7]);
        }
    }

    #pragma unroll
    for (int p = 0; p < 8; p++) {
        const int g = tile0 + rb + p;
        if (g < rows) {
            float f0, f1;
            unpack2(acc[p], f0, f1);
            f0 = fmaxf(f0, 0.f);
            f1 = fmaxf(f1, 0.f);
            ((float2*)(out + (size_t)g * 128))[cg * 32 + lane] =
                make_float2(f0, f1);
        }
    }
}

// ---------------- fused edge projection + segment-sum into m_e ----------------
// m_e[dst[e]] += relu(EF[e] @ We + be). Block 256 = 8 warps, tile 64 edges,
// 8 rows/warp, 4 cols/lane (2 col-pairs). Per warp-k: 1 LDS.128 W +
// 4 LDS.128 dup-X + 16 FMA2, zero MOVs. EE % 64 == 0.
__global__ void edge_proj_kernel(const float* __restrict__ EF,
                                 const float* __restrict__ W,
                                 const float* __restrict__ bias) {
    __shared__ __align__(16) float W_s[EDIM * 128];   // 16 KB
    __shared__ __align__(16) float X_s[EDIM * XS2];   // ~16.9 KB, duplicated
    __shared__ int dst_s[64];
    const int tid = threadIdx.x;
    const int tile0 = blockIdx.x * 64;

    for (int i = tid; i < EDIM * 128 / 4; i += 256)
        ((float4*)W_s)[i] = ((const float4*)W)[i];

    {   // stage 64 edge rows duplicated (KC = 8)
        for (int i = tid; i < 64 * (EDIM / 4); i += 256) {
            const int r = i & 63, kc = i >> 6;
            const float4 v = ((const float4*)(EF + (size_t)(tile0 + r) * EDIM))[kc];
            float* xp = &X_s[(kc * 4) * XS2 + 2 * r];
            sts_dup(xp + 0 * XS2, v.x);
            sts_dup(xp + 1 * XS2, v.y);
            sts_dup(xp + 2 * XS2, v.z);
            sts_dup(xp + 3 * XS2, v.w);
        }
    }
    if (tid < 64) dst_s[tid] = g_dst[tile0 + tid];
    __syncthreads();

    const int lane = tid & 31;
    const int w = tid >> 5;
    const int rb = w * 8;
    const unsigned long long b0 = ((const unsigned long long*)bias)[lane * 2];
    const unsigned long long b1 = ((const unsigned long long*)bias)[lane * 2 + 1];
    unsigned long long acc[8][2];
    #pragma unroll
    for (int p = 0; p < 8; p++) { acc[p][0] = b0; acc[p][1] = b1; }

    #pragma unroll
    for (int k = 0; k < EDIM; k++) {
        const ulonglong2 wp =
            *(const ulonglong2*)&W_s[k * 128 + lane * 4];
        const float* xb = &X_s[k * XS2 + 2 * rb];
        const ulonglong2 x01 = *(const ulonglong2*)(xb + 0);
        const ulonglong2 x23 = *(const ulonglong2*)(xb + 4);
        const ulonglong2 x45 = *(const ulonglong2*)(xb + 8);
        const ulonglong2 x67 = *(const ulonglong2*)(xb + 12);
        const unsigned long long xd[8] = {x01.x, x01.y, x23.x, x23.y,
                                          x45.x, x45.y, x67.x, x67.y};
        #pragma unroll
        for (int p = 0; p < 8; p++) {
            acc[p][0] = fma2(xd[p], wp.x, acc[p][0]);
            acc[p][1] = fma2(xd[p], wp.y, acc[p][1]);
        }
    }

    #pragma unroll
    for (int p = 0; p < 8; p++) {
        float4 v;
        unpack2(acc[p][0], v.x, v.y);
        unpack2(acc[p][1], v.z, v.w);
        v.x = fmaxf(v.x, 0.f); v.y = fmaxf(v.y, 0.f);
        v.z = fmaxf(v.z, 0.f); v.w = fmaxf(v.w, 0.f);
        red_add_v4(&g_me[(size_t)dst_s[rb + p] * 128 + lane * 4], v);
    }
}

// ---------------- CSR aggregation: m_x[n] = sum_{e: dst=n} x[src[e]] ----------------
// Warp per node; indices prefetched 32-wide and shuffled; output written once.
__global__ void gather_csr(const float* __restrict__ x) {
    const int lane = threadIdx.x & 31;
    const int warp = (blockIdx.x * blockDim.x + threadIdx.x) >> 5;
    const int nwarps = (gridDim.x * blockDim.x) >> 5;
    for (int n = warp; n < NN; n += nwarps) {
        const int start = g_rowptr[n];
        const int deg = g_cnt[n];
        float4 acc = make_float4(0.f, 0.f, 0.f, 0.f);
        for (int j0 = 0; j0 < deg; j0 += 32) {
            const int m = min(32, deg - j0);
            const int idx = (lane < m) ? g_csr_src[start + j0 + lane] : 0;
            for (int j = 0; j < m; j++) {
                const int s = __shfl_sync(0xffffffffu, idx, j);
                const float4 v = ((const float4*)(x + (size_t)s * 128))[lane];
                acc.x += v.x; acc.y += v.y; acc.z += v.z; acc.w += v.w;
            }
        }
        ((float4*)(g_mx + (size_t)n * 128))[lane] = acc;
    }
}

// ---------------- scores + global max ----------------
__global__ void scores_kernel(const float* __restrict__ x,
                              const float* __restrict__ Wo,
                              const float* __restrict__ bo) {
    const int lane = threadIdx.x & 31;
    const int w = threadIdx.x >> 5;
    const int nw = blockDim.x >> 5;
    const float4 wv = ((const float4*)Wo)[lane];
    const float b = *bo;
    float lmax = -3.402823466e38f;
    for (int n = blockIdx.x * nw + w; n < NN; n += gridDim.x * nw) {
        const float4 xv = ((const float4*)(x + (size_t)n * 128))[lane];
        float d = xv.x * wv.x + xv.y * wv.y + xv.z * wv.z + xv.w * wv.w;
        #pragma unroll
        for (int o = 16; o; o >>= 1) d += __shfl_down_sync(0xffffffffu, d, o);
        if (lane == 0) {
            const float sc = d + b;
            g_scores[n] = sc;
            if (sc > lmax) lmax = sc;
        }
    }
    __shared__ float sm[8];
    lmax = __shfl_sync(0xffffffffu, lmax, 0);
    if (lane == 0) sm[w] = lmax;
    __syncthreads();
    if (threadIdx.x == 0) {
        float m = sm[0];
        for (int i = 1; i < nw; i++) m = fmaxf(m, sm[i]);
        atomicMax(&g_maxbits, enc_ordered(m));
    }
}

// ---------------- sum of exp ----------------
__global__ void sum_kernel() {
    const float maxf = dec_ordered(g_maxbits);
    float s = 0.f;
    for (int n = blockIdx.x * blockDim.x + threadIdx.x; n < NN;
         n += gridDim.x * blockDim.x)
        s += expf(g_scores[n] - maxf);
    #pragma unroll
    for (int o = 16; o; o >>= 1) s += __shfl_down_sync(0xffffffffu, s, o);
    __shared__ float sm[8];
    const int lane = threadIdx.x & 31, w = threadIdx.x >> 5;
    if (lane == 0) sm[w] = s;
    __syncthreads();
    if (threadIdx.x == 0) {
        float t = 0.f;
        const int nw = blockDim.x >> 5;
        for (int i = 0; i < nw; i++) t += sm[i];
        atomicAdd(&g_sum, t);
    }
}

// ---------------- normalize ----------------
__global__ void finalize_kernel(float* __restrict__ out) {
    const float maxf = dec_ordered(g_maxbits);
    const float inv = 1.0f / g_sum;
    const int n = blockIdx.x * blockDim.x + threadIdx.x;
    if (n < NN) out[n] = expf(g_scores[n] - maxf) * inv;
}

// ---------------- launch ----------------
extern "C" void kernel_launch(void* const* d_in, const int* in_sizes, int n_in,
                              void* d_out, int out_size) {
    const float* NF = (const float*)d_in[0];
    const float* EF = (const float*)d_in[1];
    const float* Wn = (const float*)d_in[2];
    const float* bn = (const float*)d_in[3];
    const float* We = (const float*)d_in[4];
    const float* be = (const float*)d_in[5];
    const float* W1 = (const float*)d_in[6];
    const float* b1 = (const float*)d_in[7];
    const float* W2 = (const float*)d_in[8];
    const float* b2 = (const float*)d_in[9];
    const float* Wo = (const float*)d_in[10];
    const float* bo = (const float*)d_in[11];
    const void*  EI = d_in[12];
    float* out = (float*)d_out;

    float *px0, *px1, *pmx, *pme;
    cudaGetSymbolAddress((void**)&px0, g_x0);
    cudaGetSymbolAddress((void**)&px1, g_x1);
    cudaGetSymbolAddress((void**)&pmx, g_mx);
    cudaGetSymbolAddress((void**)&pme, g_me);

    const int SMEM_128 = (128 * 128 + 128 * XS2) * 4;   // ~130 KB
    const int SMEM_256 = (128 * 128 + 256 * XS2) * 4;   // ~196 KB (W chunked)
    cudaFuncSetAttribute(proj_kernel<128, false>,
                         cudaFuncAttributeMaxDynamicSharedMemorySize, SMEM_128);
    cudaFuncSetAttribute(proj_kernel<256, true>,
                         cudaFuncAttributeMaxDynamicSharedMemorySize, SMEM_256);

    const int nTilesN = (NN + 63) / 64;   // 782
    const int nTilesE = EE / 64;          // 12500

    // edge index normalization + cnt zeroing
    convert_edges<<<512, 256>>>(EI);
    // zero m_e + softmax scalars
    zero_me<<<2048, 256>>>();
    // CSR build (topology computed once, reused by both conv layers)
    hist_kernel<<<512, 256>>>();
    scan_reduce<<<NB_SCAN, 256>>>();
    scan_partials<<<1, 256>>>();
    scan_final<<<NB_SCAN, 256>>>();
    fill_kernel<<<512, 256>>>();
    // x0 = relu(NF @ Wn + bn)
    proj_kernel<128, false><<<nTilesN, 512, SMEM_128>>>(NF, nullptr, Wn, bn, px0, NN);
    // m_e = segment_sum(relu(EF @ We + be), dst)   [computed once]
    edge_proj_kernel<<<nTilesE, 256>>>(EF, We, be);
    // layer 1
    gather_csr<<<1184, 256>>>(px0);
    proj_kernel<256, true><<<nTilesN, 512, SMEM_256>>>(pmx, pme, W1, b1, px1, NN);
    // layer 2
    gather_csr<<<1184, 256>>>(px1);
    proj_kernel<256, true><<<nTilesN, 512, SMEM_256>>>(pmx, pme, W2, b2, px0, NN);
    // scores + softmax
    scores_kernel<<<512, 128>>>(px0, Wo, bo);
    sum_kernel<<<512, 256>>>();
    finalize_kernel<<<(NN + 255) / 256, 256>>>(out);
}

// round 7
// speedup vs baseline: 1.3048x; 1.3048x over previous
#include <cuda_runtime.h>
#include <cstdint>
#include <cstddef>

#define NN 50000
#define EE 800000
#define HID 128
#define EDIM 32
#define XSTR 66      // padded row-transposed X stride (even -> 8B aligned LDS.64)
#define NB_SCAN 196  // ceil(NN/256)

// ---------------- scratch (static __device__ — allocation-free) ----------------
__device__ __align__(16) float g_x0[(size_t)NN * HID];
__device__ __align__(16) float g_x1[(size_t)NN * HID];
__device__ __align__(16) float g_mx[(size_t)NN * HID];
__device__ __align__(16) float g_me[(size_t)NN * HID];
__device__ __align__(16) float g_scores[NN];
__device__ int g_src[EE];
__device__ int g_dst[EE];
__device__ int g_csr_src[EE];
__device__ int g_cnt[NN];
__device__ int g_rowptr[NN];
__device__ int g_cur[NN];
__device__ int g_partial[256];
__device__ unsigned g_maxbits;
__device__ float g_sum;

// ---------------- helpers ----------------
__device__ __forceinline__ void red_add_v4(float* addr, float4 v) {
    asm volatile("red.global.add.v4.f32 [%0], {%1,%2,%3,%4};"
                 :: "l"(addr), "f"(v.x), "f"(v.y), "f"(v.z), "f"(v.w)
                 : "memory");
}
// packed f32x2 FMA: d = a*b + c (two fp32 lanes per instruction)
__device__ __forceinline__ unsigned long long fma2(unsigned long long a,
                                                   unsigned long long b,
                                                   unsigned long long c) {
    unsigned long long d;
    asm("fma.rn.f32x2 %0, %1, %2, %3;" : "=l"(d) : "l"(a), "l"(b), "l"(c));
    return d;
}
__device__ __forceinline__ unsigned long long dup2(float s) {
    unsigned long long d;
    asm("mov.b64 %0, {%1, %1};" : "=l"(d) : "f"(s));
    return d;
}
__device__ __forceinline__ void unpack2(unsigned long long v, float& lo, float& hi) {
    asm("mov.b64 {%0, %1}, %2;" : "=f"(lo), "=f"(hi) : "l"(v));
}
__device__ __forceinline__ unsigned enc_ordered(float f) {
    unsigned b = __float_as_uint(f);
    return (b & 0x80000000u) ? ~b : (b | 0x80000000u);
}
__device__ __forceinline__ float dec_ordered(unsigned u) {
    unsigned b = (u & 0x80000000u) ? (u ^ 0x80000000u) : ~u;
    return __uint_as_float(b);
}

// ---------------- edge index normalization + cnt zeroing ----------------
__global__ void convert_edges(const void* __restrict__ ei) {
    __shared__ int is64;
    if (threadIdx.x == 0) {
        const int* p = (const int*)ei;
        int z = 0;
        #pragma unroll
        for (int i = 0; i < 64; i++) z |= p[2 * i + 1];
        is64 = (z == 0);
    }
    __syncthreads();
    const int idx = blockIdx.x * blockDim.x + threadIdx.x;
    const int stride = gridDim.x * blockDim.x;
    for (int i = idx; i < NN; i += stride) g_cnt[i] = 0;
    if (is64) {
        const long long* p = (const long long*)ei;
        for (int e = idx; e < EE; e += stride) {
            g_src[e] = (int)p[e];
            g_dst[e] = (int)p[EE + e];
        }
    } else {
        const int* p = (const int*)ei;
        for (int e = idx; e < EE; e += stride) {
            g_src[e] = p[e];
            g_dst[e] = p[EE + e];
        }
    }
}

// ---------------- CSR build ----------------
__global__ void hist_kernel() {
    const int idx = blockIdx.x * blockDim.x + threadIdx.x;
    const int stride = gridDim.x * blockDim.x;
    for (int e = idx; e < EE; e += stride) atomicAdd(&g_cnt[g_dst[e]], 1);
}

__global__ void scan_reduce() {
    __shared__ int sh[256];
    const int t = threadIdx.x;
    const int i = blockIdx.x * 256 + t;
    sh[t] = (i < NN) ? g_cnt[i] : 0;
    __syncthreads();
    #pragma unroll
    for (int o = 128; o; o >>= 1) {
        if (t < o) sh[t] += sh[t + o];
        __syncthreads();
    }
    if (t == 0) g_partial[blockIdx.x] = sh[0];
}

__global__ void scan_partials() {
    __shared__ int sh[256];
    const int t = threadIdx.x;
    const int v = (t < NB_SCAN) ? g_partial[t] : 0;
    sh[t] = v;
    __syncthreads();
    #pragma unroll
    for (int off = 1; off < 256; off <<= 1) {
        int a = (t >= off) ? sh[t - off] : 0;
        __syncthreads();
        sh[t] += a;
        __syncthreads();
    }
    g_partial[t] = sh[t] - v;   // exclusive
}

__global__ void scan_final() {
    __shared__ int sh[256];
    const int t = threadIdx.x;
    const int i = blockIdx.x * 256 + t;
    const int v = (i < NN) ? g_cnt[i] : 0;
    sh[t] = v;
    __syncthreads();
    #pragma unroll
    for (int off = 1; off < 256; off <<= 1) {
        int a = (t >= off) ? sh[t - off] : 0;
        __syncthreads();
        sh[t] += a;
        __syncthreads();
    }
    if (i < NN) {
        const int excl = sh[t] - v + g_partial[blockIdx.x];
        g_rowptr[i] = excl;
        g_cur[i] = excl;
    }
}

__global__ void fill_kernel() {
    const int idx = blockIdx.x * blockDim.x + threadIdx.x;
    const int stride = gridDim.x * blockDim.x;
    for (int e = idx; e < EE; e += stride) {
        const int d = g_dst[e];
        const int p = atomicAdd(&g_cur[d], 1);
        g_csr_src[p] = g_src[e];
    }
}

// ---------------- zero m_e + scalars ----------------
__global__ void zero_me() {
    const int n4 = NN * HID / 4;
    float4* a = (float4*)g_me;
    const float4 z = make_float4(0.f, 0.f, 0.f, 0.f);
    for (int i = blockIdx.x * blockDim.x + threadIdx.x; i < n4;
         i += gridDim.x * blockDim.x)
        a[i] = z;
    if (blockIdx.x == 0 && threadIdx.x == 0) { g_maxbits = 0u; g_sum = 0.f; }
}

// ---------------- f32x2 row-projection GEMM (R3 geometry): out = relu(in @ W + b) ----
// Block = 256 threads = 8 warps. Tile = 64 rows x 128 cols.
// Warp w owns rows [w*8,+8) as 4 row-PAIRS; lane owns cols [lane*4,+4).
// X staged TRANSPOSED (X_s[k*XSTR + row]); inner loop per warp-k:
// 16 FMA2 (=32 FMAs) + 4 dup movs + 1 LDS.128 W + 4 bcast LDS.64 X.
template <int K, bool CONCAT>
__global__ void proj_kernel(const float* __restrict__ in0,
                            const float* __restrict__ in1,
                            const float* __restrict__ W,
                            const float* __restrict__ bias,
                            float* __restrict__ out, int rows) {
    extern __shared__ float sh[];
    float* W_s = sh;             // K*128 floats
    float* X_s = sh + K * 128;   // K*XSTR floats (transposed, padded)
    const int tid = threadIdx.x;

    {   // stage W (coalesced float4)
        const float4* Wg = (const float4*)W;
        float4* Ws4 = (float4*)W_s;
        const int n4 = K * 128 / 4;
        for (int i = tid; i < n4; i += 256) Ws4[i] = Wg[i];
    }
    const int tile0 = blockIdx.x * 64;
    {   // stage 64 rows transposed
        const int KC = K / 4;
        for (int i = tid; i < 64 * KC; i += 256) {
            const int r = i & 63, kc = i >> 6;
            const int g = tile0 + r;
            float4 v = make_float4(0.f, 0.f, 0.f, 0.f);
            if (g < rows) {
                if (CONCAT) {
                    v = (kc < 32) ? ((const float4*)(in0 + (size_t)g * 128))[kc]
                                  : ((const float4*)(in1 + (size_t)g * 128))[kc - 32];
                } else {
                    v = ((const float4*)(in0 + (size_t)g * K))[kc];
                }
            }
            float* xp = &X_s[(kc * 4) * XSTR + r];
            xp[0 * XSTR] = v.x;
            xp[1 * XSTR] = v.y;
            xp[2 * XSTR] = v.z;
            xp[3 * XSTR] = v.w;
        }
    }
    __syncthreads();

    const int lane = tid & 31;
    const int w = tid >> 5;
    const int rb = w * 8;
    const float4 bias4 = ((const float4*)bias)[lane];
    unsigned long long acc[4][4];
    {
        const unsigned long long b0 = dup2(bias4.x), b1 = dup2(bias4.y);
        const unsigned long long b2 = dup2(bias4.z), b3 = dup2(bias4.w);
        #pragma unroll
        for (int p = 0; p < 4; p++) {
            acc[p][0] = b0; acc[p][1] = b1; acc[p][2] = b2; acc[p][3] = b3;
        }
    }

    #pragma unroll 4
    for (int k = 0; k < K; k++) {
        const float4 wv = ((const float4*)&W_s[k * 128])[lane];
        const unsigned long long w0 = dup2(wv.x), w1 = dup2(wv.y);
        const unsigned long long w2 = dup2(wv.z), w3 = dup2(wv.w);
        const float* xb = &X_s[k * XSTR + rb];
        #pragma unroll
        for (int p = 0; p < 4; p++) {
            const unsigned long long xp = *(const unsigned long long*)(xb + 2 * p);
            acc[p][0] = fma2(xp, w0, acc[p][0]);
            acc[p][1] = fma2(xp, w1, acc[p][1]);
            acc[p][2] = fma2(xp, w2, acc[p][2]);
            acc[p][3] = fma2(xp, w3, acc[p][3]);
        }
    }

    #pragma unroll
    for (int p = 0; p < 4; p++) {
        float4 v0, v1;
        unpack2(acc[p][0], v0.x, v1.x);
        unpack2(acc[p][1], v0.y, v1.y);
        unpack2(acc[p][2], v0.z, v1.z);
        unpack2(acc[p][3], v0.w, v1.w);
        const int g0 = tile0 + rb + 2 * p;
        if (g0 < rows) {
            v0.x = fmaxf(v0.x, 0.f); v0.y = fmaxf(v0.y, 0.f);
            v0.z = fmaxf(v0.z, 0.f); v0.w = fmaxf(v0.w, 0.f);
            ((float4*)(out + (size_t)g0 * 128))[lane] = v0;
        }
        if (g0 + 1 < rows) {
            v1.x = fmaxf(v1.x, 0.f); v1.y = fmaxf(v1.y, 0.f);
            v1.z = fmaxf(v1.z, 0.f); v1.w = fmaxf(v1.w, 0.f);
            ((float4*)(out + (size_t)(g0 + 1) * 128))[lane] = v1;
        }
    }
}

// ---------------- fused edge projection + segment-sum into m_e (R3 geometry) -------
__global__ void edge_proj_kernel(const float* __restrict__ EF,
                                 const float* __restrict__ W,
                                 const float* __restrict__ bias) {
    __shared__ __align__(16) float W_s[EDIM * 128];     // 16 KB
    __shared__ __align__(16) float X_s[EDIM * XSTR];    // 8.25 KB, transposed
    __shared__ int dst_s[64];
    const int tid = threadIdx.x;

    for (int i = tid; i < EDIM * 128 / 4; i += 256)
        ((float4*)W_s)[i] = ((const float4*)W)[i];

    const int tile0 = blockIdx.x * 64;
    {   // transpose-stage 64 edge rows (KC = 8)
        for (int i = tid; i < 64 * (EDIM / 4); i += 256) {
            const int r = i & 63, kc = i >> 6;
            const float4 v = ((const float4*)(EF + (size_t)(tile0 + r) * EDIM))[kc];
            float* xp = &X_s[(kc * 4) * XSTR + r];
            xp[0 * XSTR] = v.x;
            xp[1 * XSTR] = v.y;
            xp[2 * XSTR] = v.z;
            xp[3 * XSTR] = v.w;
        }
    }
    if (tid < 64) dst_s[tid] = g_dst[tile0 + tid];
    __syncthreads();

    const int lane = tid & 31;
    const int w = tid >> 5;
    const int rb = w * 8;
    const float4 bias4 = ((const float4*)bias)[lane];
    unsigned long long acc[4][4];
    {
        const unsigned long long b0 = dup2(bias4.x), b1 = dup2(bias4.y);
        const unsigned long long b2 = dup2(bias4.z), b3 = dup2(bias4.w);
        #pragma unroll
        for (int p = 0; p < 4; p++) {
            acc[p][0] = b0; acc[p][1] = b1; acc[p][2] = b2; acc[p][3] = b3;
        }
    }

    #pragma unroll
    for (int k = 0; k < EDIM; k++) {
        const float4 wv = ((const float4*)&W_s[k * 128])[lane];
        const unsigned long long w0 = dup2(wv.x), w1 = dup2(wv.y);
        const unsigned long long w2 = dup2(wv.z), w3 = dup2(wv.w);
        const float* xb = &X_s[k * XSTR + rb];
        #pragma unroll
        for (int p = 0; p < 4; p++) {
            const unsigned long long xp = *(const unsigned long long*)(xb + 2 * p);
            acc[p][0] = fma2(xp, w0, acc[p][0]);
            acc[p][1] = fma2(xp, w1, acc[p][1]);
            acc[p][2] = fma2(xp, w2, acc[p][2]);
            acc[p][3] = fma2(xp, w3, acc[p][3]);
        }
    }

    #pragma unroll
    for (int p = 0; p < 4; p++) {
        float4 v0, v1;
        unpack2(acc[p][0], v0.x, v1.x);
        unpack2(acc[p][1], v0.y, v1.y);
        unpack2(acc[p][2], v0.z, v1.z);
        unpack2(acc[p][3], v0.w, v1.w);
        v0.x = fmaxf(v0.x, 0.f); v0.y = fmaxf(v0.y, 0.f);
        v0.z = fmaxf(v0.z, 0.f); v0.w = fmaxf(v0.w, 0.f);
        v1.x = fmaxf(v1.x, 0.f); v1.y = fmaxf(v1.y, 0.f);
        v1.z = fmaxf(v1.z, 0.f); v1.w = fmaxf(v1.w, 0.f);
        const int r0 = rb + 2 * p;
        red_add_v4(&g_me[(size_t)dst_s[r0] * 128 + lane * 4], v0);
        red_add_v4(&g_me[(size_t)dst_s[r0 + 1] * 128 + lane * 4], v1);
    }
}

// ---------------- CSR aggregation: m_x[n] = sum_{e: dst=n} x[src[e]] ----------------
// Warp per node; dual accumulators + unroll-2 so the FADD chain is 2 cyc/neighbor
// and the independent LDGs pipeline. Output written exactly once (no atomics,
// no pre-zero pass).
__global__ void gather_csr(const float* __restrict__ x) {
    const int lane = threadIdx.x & 31;
    const int warp = (blockIdx.x * blockDim.x + threadIdx.x) >> 5;
    const int nwarps = (gridDim.x * blockDim.x) >> 5;
    for (int n = warp; n < NN; n += nwarps) {
        const int start = g_rowptr[n];
        const int deg = g_cnt[n];
        float4 a0 = make_float4(0.f, 0.f, 0.f, 0.f);
        float4 a1 = make_float4(0.f, 0.f, 0.f, 0.f);
        for (int j0 = 0; j0 < deg; j0 += 32) {
            const int m = min(32, deg - j0);
            const int idx = (lane < m) ? g_csr_src[start + j0 + lane] : 0;
            int j = 0;
            for (; j + 1 < m; j += 2) {
                const int s0 = __shfl_sync(0xffffffffu, idx, j);
                const int s1 = __shfl_sync(0xffffffffu, idx, j + 1);
                const float4 v0 = ((const float4*)(x + (size_t)s0 * 128))[lane];
                const float4 v1 = ((const float4*)(x + (size_t)s1 * 128))[lane];
                a0.x += v0.x; a0.y += v0.y; a0.z += v0.z; a0.w += v0.w;
                a1.x += v1.x; a1.y += v1.y; a1.z += v1.z; a1.w += v1.w;
            }
            if (j < m) {
                const int s0 = __shfl_sync(0xffffffffu, idx, j);
                const float4 v0 = ((const float4*)(x + (size_t)s0 * 128))[lane];
                a0.x += v0.x; a0.y += v0.y; a0.z += v0.z; a0.w += v0.w;
            }
        }
        a0.x += a1.x; a0.y += a1.y; a0.z += a1.z; a0.w += a1.w;
        ((float4*)(g_mx + (size_t)n * 128))[lane] = a0;
    }
}

// ---------------- scores + global max ----------------
__global__ void scores_kernel(const float* __restrict__ x,
                              const float* __restrict__ Wo,
                              const float* __restrict__ bo) {
    const int lane = threadIdx.x & 31;
    const int w = threadIdx.x >> 5;
    const int nw = blockDim.x >> 5;
    const float4 wv = ((const float4*)Wo)[lane];
    const float b = *bo;
    float lmax = -3.402823466e38f;
    for (int n = blockIdx.x * nw + w; n < NN; n += gridDim.x * nw) {
        const float4 xv = ((const float4*)(x + (size_t)n * 128))[lane];
        float d = xv.x * wv.x + xv.y * wv.y + xv.z * wv.z + xv.w * wv.w;
        #pragma unroll
        for (int o = 16; o; o >>= 1) d += __shfl_down_sync(0xffffffffu, d, o);
        if (lane == 0) {
            const float sc = d + b;
            g_scores[n] = sc;
            if (sc > lmax) lmax = sc;
        }
    }
    __shared__ float sm[8];
    lmax = __shfl_sync(0xffffffffu, lmax, 0);
    if (lane == 0) sm[w] = lmax;
    __syncthreads();
    if (threadIdx.x == 0) {
        float m = sm[0];
        for (int i = 1; i < nw; i++) m = fmaxf(m, sm[i]);
        atomicMax(&g_maxbits, enc_ordered(m));
    }
}

// ---------------- sum of exp ----------------
__global__ void sum_kernel() {
    const float maxf = dec_ordered(g_maxbits);
    float s = 0.f;
    for (int n = blockIdx.x * blockDim.x + threadIdx.x; n < NN;
         n += gridDim.x * blockDim.x)
        s += expf(g_scores[n] - maxf);
    #pragma unroll
    for (int o = 16; o; o >>= 1) s += __shfl_down_sync(0xffffffffu, s, o);
    __shared__ float sm[8];
    const int lane = threadIdx.x & 31, w = threadIdx.x >> 5;
    if (lane == 0) sm[w] = s;
    __syncthreads();
    if (threadIdx.x == 0) {
        float t = 0.f;
        const int nw = blockDim.x >> 5;
        for (int i = 0; i < nw; i++) t += sm[i];
        atomicAdd(&g_sum, t);
    }
}

// ---------------- normalize ----------------
__global__ void finalize_kernel(float* __restrict__ out) {
    const float maxf = dec_ordered(g_maxbits);
    const float inv = 1.0f / g_sum;
    const int n = blockIdx.x * blockDim.x + threadIdx.x;
    if (n < NN) out[n] = expf(g_scores[n] - maxf) * inv;
}

// ---------------- launch ----------------
extern "C" void kernel_launch(void* const* d_in, const int* in_sizes, int n_in,
                              void* d_out, int out_size) {
    const float* NF = (const float*)d_in[0];
    const float* EF = (const float*)d_in[1];
    const float* Wn = (const float*)d_in[2];
    const float* bn = (const float*)d_in[3];
    const float* We = (const float*)d_in[4];
    const float* be = (const float*)d_in[5];
    const float* W1 = (const float*)d_in[6];
    const float* b1 = (const float*)d_in[7];
    const float* W2 = (const float*)d_in[8];
    const float* b2 = (const float*)d_in[9];
    const float* Wo = (const float*)d_in[10];
    const float* bo = (const float*)d_in[11];
    const void*  EI = d_in[12];
    float* out = (float*)d_out;

    float *px0, *px1, *pmx, *pme;
    cudaGetSymbolAddress((void**)&px0, g_x0);
    cudaGetSymbolAddress((void**)&px1, g_x1);
    cudaGetSymbolAddress((void**)&pmx, g_mx);
    cudaGetSymbolAddress((void**)&pme, g_me);

    const int SMEM_128 = (128 * 128 + 128 * XSTR) * 4;   // ~97 KB
    const int SMEM_256 = (256 * 128 + 256 * XSTR) * 4;   // ~194 KB
    cudaFuncSetAttribute(proj_kernel<128, false>,
                         cudaFuncAttributeMaxDynamicSharedMemorySize, SMEM_128);
    cudaFuncSetAttribute(proj_kernel<256, true>,
                         cudaFuncAttributeMaxDynamicSharedMemorySize, SMEM_256);

    const int nTilesN = (NN + 63) / 64;   // 782
    const int nTilesE = EE / 64;          // 12500

    // edge index normalization + cnt zeroing
    convert_edges<<<512, 256>>>(EI);
    // zero m_e + softmax scalars
    zero_me<<<2048, 256>>>();
    // CSR build (topology computed once, reused by both conv layers)
    hist_kernel<<<512, 256>>>();
    scan_reduce<<<NB_SCAN, 256>>>();
    scan_partials<<<1, 256>>>();
    scan_final<<<NB_SCAN, 256>>>();
    fill_kernel<<<512, 256>>>();
    // x0 = relu(NF @ Wn + bn)
    proj_kernel<128, false><<<nTilesN, 256, SMEM_128>>>(NF, nullptr, Wn, bn, px0, NN);
    // m_e = segment_sum(relu(EF @ We + be), dst)   [computed once]
    edge_proj_kernel<<<nTilesE, 256>>>(EF, We, be);
    // layer 1
    gather_csr<<<1184, 256>>>(px0);
    proj_kernel<256, true><<<nTilesN, 256, SMEM_256>>>(pmx, pme, W1, b1, px1, NN);
    // layer 2
    gather_csr<<<1184, 256>>>(px1);
    proj_kernel<256, true><<<nTilesN, 256, SMEM_256>>>(pmx, pme, W2, b2, px0, NN);
    // scores + softmax
    scores_kernel<<<512, 128>>>(px0, Wo, bo);
    sum_kernel<<<512, 256>>>();
    finalize_kernel<<<(NN + 255) / 256, 256>>>(out);
}

// round 8
// speedup vs baseline: 1.3219x; 1.0131x over previous
#include <cuda_runtime.h>
#include <cstdint>
#include <cstddef>

#define NN 50000
#define EE 800000
#define HID 128
#define EDIM 32
#define XSTR 68      // transposed-X stride; k*XSTR & row-base both 16B-aligned -> LDS.128
#define NB_SCAN 196  // ceil(NN/256)

// ---------------- scratch (static __device__ — allocation-free) ----------------
__device__ __align__(16) float g_x0[(size_t)NN * HID];
__device__ __align__(16) float g_x1[(size_t)NN * HID];
__device__ __align__(16) float g_mx[(size_t)NN * HID];
__device__ __align__(16) float g_me[(size_t)NN * HID];
__device__ __align__(16) float g_scores[NN];
__device__ int g_src[EE];
__device__ int g_dst[EE];
__device__ int g_csr_src[EE];
__device__ int g_cnt[NN];
__device__ int g_rowptr[NN];
__device__ int g_cur[NN];
__device__ int g_partial[256];
__device__ unsigned g_maxbits;
__device__ float g_sum;

// ---------------- helpers ----------------
__device__ __forceinline__ void red_add_v4(float* addr, float4 v) {
    asm volatile("red.global.add.v4.f32 [%0], {%1,%2,%3,%4};"
                 :: "l"(addr), "f"(v.x), "f"(v.y), "f"(v.z), "f"(v.w)
                 : "memory");
}
// packed f32x2 FMA: d = a*b + c (two fp32 lanes per instruction)
__device__ __forceinline__ unsigned long long fma2(unsigned long long a,
                                                   unsigned long long b,
                                                   unsigned long long c) {
    unsigned long long d;
    asm("fma.rn.f32x2 %0, %1, %2, %3;" : "=l"(d) : "l"(a), "l"(b), "l"(c));
    return d;
}
__device__ __forceinline__ unsigned long long dup2(float s) {
    unsigned long long d;
    asm("mov.b64 %0, {%1, %1};" : "=l"(d) : "f"(s));
    return d;
}
__device__ __forceinline__ void unpack2(unsigned long long v, float& lo, float& hi) {
    asm("mov.b64 {%0, %1}, %2;" : "=f"(lo), "=f"(hi) : "l"(v));
}
__device__ __forceinline__ unsigned enc_ordered(float f) {
    unsigned b = __float_as_uint(f);
    return (b & 0x80000000u) ? ~b : (b | 0x80000000u);
}
__device__ __forceinline__ float dec_ordered(unsigned u) {
    unsigned b = (u & 0x80000000u) ? (u ^ 0x80000000u) : ~u;
    return __uint_as_float(b);
}

// ---------------- edge index normalization + cnt zeroing ----------------
__global__ void convert_edges(const void* __restrict__ ei) {
    __shared__ int is64;
    if (threadIdx.x == 0) {
        const int* p = (const int*)ei;
        int z = 0;
        #pragma unroll
        for (int i = 0; i < 64; i++) z |= p[2 * i + 1];
        is64 = (z == 0);
    }
    __syncthreads();
    const int idx = blockIdx.x * blockDim.x + threadIdx.x;
    const int stride = gridDim.x * blockDim.x;
    for (int i = idx; i < NN; i += stride) g_cnt[i] = 0;
    if (is64) {
        const long long* p = (const long long*)ei;
        for (int e = idx; e < EE; e += stride) {
            g_src[e] = (int)p[e];
            g_dst[e] = (int)p[EE + e];
        }
    } else {
        const int* p = (const int*)ei;
        for (int e = idx; e < EE; e += stride) {
            g_src[e] = p[e];
            g_dst[e] = p[EE + e];
        }
    }
}

// ---------------- CSR build ----------------
__global__ void hist_kernel() {
    const int idx = blockIdx.x * blockDim.x + threadIdx.x;
    const int stride = gridDim.x * blockDim.x;
    for (int e = idx; e < EE; e += stride) atomicAdd(&g_cnt[g_dst[e]], 1);
}

__global__ void scan_reduce() {
    __shared__ int sh[256];
    const int t = threadIdx.x;
    const int i = blockIdx.x * 256 + t;
    sh[t] = (i < NN) ? g_cnt[i] : 0;
    __syncthreads();
    #pragma unroll
    for (int o = 128; o; o >>= 1) {
        if (t < o) sh[t] += sh[t + o];
        __syncthreads();
    }
    if (t == 0) g_partial[blockIdx.x] = sh[0];
}

__global__ void scan_partials() {
    __shared__ int sh[256];
    const int t = threadIdx.x;
    const int v = (t < NB_SCAN) ? g_partial[t] : 0;
    sh[t] = v;
    __syncthreads();
    #pragma unroll
    for (int off = 1; off < 256; off <<= 1) {
        int a = (t >= off) ? sh[t - off] : 0;
        __syncthreads();
        sh[t] += a;
        __syncthreads();
    }
    g_partial[t] = sh[t] - v;   // exclusive
}

__global__ void scan_final() {
    __shared__ int sh[256];
    const int t = threadIdx.x;
    const int i = blockIdx.x * 256 + t;
    const int v = (i < NN) ? g_cnt[i] : 0;
    sh[t] = v;
    __syncthreads();
    #pragma unroll
    for (int off = 1; off < 256; off <<= 1) {
        int a = (t >= off) ? sh[t - off] : 0;
        __syncthreads();
        sh[t] += a;
        __syncthreads();
    }
    if (i < NN) {
        const int excl = sh[t] - v + g_partial[blockIdx.x];
        g_rowptr[i] = excl;
        g_cur[i] = excl;
    }
}

__global__ void fill_kernel() {
    const int idx = blockIdx.x * blockDim.x + threadIdx.x;
    const int stride = gridDim.x * blockDim.x;
    for (int e = idx; e < EE; e += stride) {
        const int d = g_dst[e];
        const int p = atomicAdd(&g_cur[d], 1);
        g_csr_src[p] = g_src[e];
    }
}

// ---------------- zero m_e + scalars ----------------
__global__ void zero_me() {
    const int n4 = NN * HID / 4;
    float4* a = (float4*)g_me;
    const float4 z = make_float4(0.f, 0.f, 0.f, 0.f);
    for (int i = blockIdx.x * blockDim.x + threadIdx.x; i < n4;
         i += gridDim.x * blockDim.x)
        a[i] = z;
    if (blockIdx.x == 0 && threadIdx.x == 0) { g_maxbits = 0u; g_sum = 0.f; }
}

// ---------------- f32x2 row-projection GEMM: out = relu(in @ W + b) ----------------
// Block = 256 threads = 8 warps. Tile = 64 rows x 128 cols.
// Warp w owns rows [w*8,+8) as 4 row-PAIRS; lane owns cols [lane*4,+4).
// X staged TRANSPOSED (X_s[k*XSTR + row], XSTR=68 -> 16B aligned). Per warp-k:
// 1 LDS.128 W (4 wf) + 2 broadcast LDS.128 X (2 wf) + 4 dup movs + 16 FMA2.
// 6 wavefronts vs 8 fma cycles -> fma-pipe bound.
template <int K, bool CONCAT>
__global__ void proj_kernel(const float* __restrict__ in0,
                            const float* __restrict__ in1,
                            const float* __restrict__ W,
                            const float* __restrict__ bias,
                            float* __restrict__ out, int rows) {
    extern __shared__ float sh[];
    float* W_s = sh;             // K*128 floats
    float* X_s = sh + K * 128;   // K*XSTR floats (transposed, padded)
    const int tid = threadIdx.x;

    {   // stage W (coalesced float4)
        const float4* Wg = (const float4*)W;
        float4* Ws4 = (float4*)W_s;
        const int n4 = K * 128 / 4;
        for (int i = tid; i < n4; i += 256) Ws4[i] = Wg[i];
    }
    const int tile0 = blockIdx.x * 64;
    {   // stage 64 rows transposed
        const int KC = K / 4;
        for (int i = tid; i < 64 * KC; i += 256) {
            const int r = i & 63, kc = i >> 6;
            const int g = tile0 + r;
            float4 v = make_float4(0.f, 0.f, 0.f, 0.f);
            if (g < rows) {
                if (CONCAT) {
                    v = (kc < 32) ? ((const float4*)(in0 + (size_t)g * 128))[kc]
                                  : ((const float4*)(in1 + (size_t)g * 128))[kc - 32];
                } else {
                    v = ((const float4*)(in0 + (size_t)g * K))[kc];
                }
            }
            float* xp = &X_s[(kc * 4) * XSTR + r];
            xp[0 * XSTR] = v.x;
            xp[1 * XSTR] = v.y;
            xp[2 * XSTR] = v.z;
            xp[3 * XSTR] = v.w;
        }
    }
    __syncthreads();

    const int lane = tid & 31;
    const int w = tid >> 5;
    const int rb = w * 8;
    const float4 bias4 = ((const float4*)bias)[lane];
    unsigned long long acc[4][4];
    {
        const unsigned long long b0 = dup2(bias4.x), b1 = dup2(bias4.y);
        const unsigned long long b2 = dup2(bias4.z), b3 = dup2(bias4.w);
        #pragma unroll
        for (int p = 0; p < 4; p++) {
            acc[p][0] = b0; acc[p][1] = b1; acc[p][2] = b2; acc[p][3] = b3;
        }
    }

    #pragma unroll 4
    for (int k = 0; k < K; k++) {
        const float4 wv = ((const float4*)&W_s[k * 128])[lane];
        const unsigned long long w0 = dup2(wv.x), w1 = dup2(wv.y);
        const unsigned long long w2 = dup2(wv.z), w3 = dup2(wv.w);
        const float* xb = &X_s[k * XSTR + rb];
        const ulonglong2 xlo = *(const ulonglong2*)(xb + 0);  // pairs 0,1
        const ulonglong2 xhi = *(const ulonglong2*)(xb + 4);  // pairs 2,3
        const unsigned long long xp[4] = {xlo.x, xlo.y, xhi.x, xhi.y};
        #pragma unroll
        for (int p = 0; p < 4; p++) {
            acc[p][0] = fma2(xp[p], w0, acc[p][0]);
            acc[p][1] = fma2(xp[p], w1, acc[p][1]);
            acc[p][2] = fma2(xp[p], w2, acc[p][2]);
            acc[p][3] = fma2(xp[p], w3, acc[p][3]);
        }
    }

    #pragma unroll
    for (int p = 0; p < 4; p++) {
        float4 v0, v1;
        unpack2(acc[p][0], v0.x, v1.x);
        unpack2(acc[p][1], v0.y, v1.y);
        unpack2(acc[p][2], v0.z, v1.z);
        unpack2(acc[p][3], v0.w, v1.w);
        const int g0 = tile0 + rb + 2 * p;
        if (g0 < rows) {
            v0.x = fmaxf(v0.x, 0.f); v0.y = fmaxf(v0.y, 0.f);
            v0.z = fmaxf(v0.z, 0.f); v0.w = fmaxf(v0.w, 0.f);
            ((float4*)(out + (size_t)g0 * 128))[lane] = v0;
        }
        if (g0 + 1 < rows) {
            v1.x = fmaxf(v1.x, 0.f); v1.y = fmaxf(v1.y, 0.f);
            v1.z = fmaxf(v1.z, 0.f); v1.w = fmaxf(v1.w, 0.f);
            ((float4*)(out + (size_t)(g0 + 1) * 128))[lane] = v1;
        }
    }
}

// ---------------- fused edge projection + segment-sum into m_e ----------------
__global__ void edge_proj_kernel(const float* __restrict__ EF,
                                 const float* __restrict__ W,
                                 const float* __restrict__ bias) {
    __shared__ __align__(16) float W_s[EDIM * 128];     // 16 KB
    __shared__ __align__(16) float X_s[EDIM * XSTR];    // 8.5 KB, transposed
    __shared__ int dst_s[64];
    const int tid = threadIdx.x;

    for (int i = tid; i < EDIM * 128 / 4; i += 256)
        ((float4*)W_s)[i] = ((const float4*)W)[i];

    const int tile0 = blockIdx.x * 64;
    {   // transpose-stage 64 edge rows (KC = 8)
        for (int i = tid; i < 64 * (EDIM / 4); i += 256) {
            const int r = i & 63, kc = i >> 6;
            const float4 v = ((const float4*)(EF + (size_t)(tile0 + r) * EDIM))[kc];
            float* xp = &X_s[(kc * 4) * XSTR + r];
            xp[0 * XSTR] = v.x;
            xp[1 * XSTR] = v.y;
            xp[2 * XSTR] = v.z;
            xp[3 * XSTR] = v.w;
        }
    }
    if (tid < 64) dst_s[tid] = g_dst[tile0 + tid];
    __syncthreads();

    const int lane = tid & 31;
    const int w = tid >> 5;
    const int rb = w * 8;
    const float4 bias4 = ((const float4*)bias)[lane];
    unsigned long long acc[4][4];
    {
        const unsigned long long b0 = dup2(bias4.x), b1 = dup2(bias4.y);
        const unsigned long long b2 = dup2(bias4.z), b3 = dup2(bias4.w);
        #pragma unroll
        for (int p = 0; p < 4; p++) {
            acc[p][0] = b0; acc[p][1] = b1; acc[p][2] = b2; acc[p][3] = b3;
        }
    }

    #pragma unroll
    for (int k = 0; k < EDIM; k++) {
        const float4 wv = ((const float4*)&W_s[k * 128])[lane];
        const unsigned long long w0 = dup2(wv.x), w1 = dup2(wv.y);
        const unsigned long long w2 = dup2(wv.z), w3 = dup2(wv.w);
        const float* xb = &X_s[k * XSTR + rb];
        const ulonglong2 xlo = *(const ulonglong2*)(xb + 0);
        const ulonglong2 xhi = *(const ulonglong2*)(xb + 4);
        const unsigned long long xp[4] = {xlo.x, xlo.y, xhi.x, xhi.y};
        #pragma unroll
        for (int p = 0; p < 4; p++) {
            acc[p][0] = fma2(xp[p], w0, acc[p][0]);
            acc[p][1] = fma2(xp[p], w1, acc[p][1]);
            acc[p][2] = fma2(xp[p], w2, acc[p][2]);
            acc[p][3] = fma2(xp[p], w3, acc[p][3]);
        }
    }

    #pragma unroll
    for (int p = 0; p < 4; p++) {
        float4 v0, v1;
        unpack2(acc[p][0], v0.x, v1.x);
        unpack2(acc[p][1], v0.y, v1.y);
        unpack2(acc[p][2], v0.z, v1.z);
        unpack2(acc[p][3], v0.w, v1.w);
        v0.x = fmaxf(v0.x, 0.f); v0.y = fmaxf(v0.y, 0.f);
        v0.z = fmaxf(v0.z, 0.f); v0.w = fmaxf(v0.w, 0.f);
        v1.x = fmaxf(v1.x, 0.f); v1.y = fmaxf(v1.y, 0.f);
        v1.z = fmaxf(v1.z, 0.f); v1.w = fmaxf(v1.w, 0.f);
        const int r0 = rb + 2 * p;
        red_add_v4(&g_me[(size_t)dst_s[r0] * 128 + lane * 4], v0);
        red_add_v4(&g_me[(size_t)dst_s[r0 + 1] * 128 + lane * 4], v1);
    }
}

// ---------------- CSR aggregation: m_x[n] = sum_{e: dst=n} x[src[e]] ----------------
__global__ void gather_csr(const float* __restrict__ x) {
    const int lane = threadIdx.x & 31;
    const int warp = (blockIdx.x * blockDim.x + threadIdx.x) >> 5;
    const int nwarps = (gridDim.x * blockDim.x) >> 5;
    for (int n = warp; n < NN; n += nwarps) {
        const int start = g_rowptr[n];
        const int deg = g_cnt[n];
        float4 a0 = make_float4(0.f, 0.f, 0.f, 0.f);
        float4 a1 = make_float4(0.f, 0.f, 0.f, 0.f);
        for (int j0 = 0; j0 < deg; j0 += 32) {
            const int m = min(32, deg - j0);
            const int idx = (lane < m) ? g_csr_src[start + j0 + lane] : 0;
            int j = 0;
            for (; j + 1 < m; j += 2) {
                const int s0 = __shfl_sync(0xffffffffu, idx, j);
                const int s1 = __shfl_sync(0xffffffffu, idx, j + 1);
                const float4 v0 = ((const float4*)(x + (size_t)s0 * 128))[lane];
                const float4 v1 = ((const float4*)(x + (size_t)s1 * 128))[lane];
                a0.x += v0.x; a0.y += v0.y; a0.z += v0.z; a0.w += v0.w;
                a1.x += v1.x; a1.y += v1.y; a1.z += v1.z; a1.w += v1.w;
            }
            if (j < m) {
                const int s0 = __shfl_sync(0xffffffffu, idx, j);
                const float4 v0 = ((const float4*)(x + (size_t)s0 * 128))[lane];
                a0.x += v0.x; a0.y += v0.y; a0.z += v0.z; a0.w += v0.w;
            }
        }
        a0.x += a1.x; a0.y += a1.y; a0.z += a1.z; a0.w += a1.w;
        ((float4*)(g_mx + (size_t)n * 128))[lane] = a0;
    }
}

// ---------------- scores + global max ----------------
__global__ void scores_kernel(const float* __restrict__ x,
                              const float* __restrict__ Wo,
                              const float* __restrict__ bo) {
    const int lane = threadIdx.x & 31;
    const int w = threadIdx.x >> 5;
    const int nw = blockDim.x >> 5;
    const float4 wv = ((const float4*)Wo)[lane];
    const float b = *bo;
    float lmax = -3.402823466e38f;
    for (int n = blockIdx.x * nw + w; n < NN; n += gridDim.x * nw) {
        const float4 xv = ((const float4*)(x + (size_t)n * 128))[lane];
        float d = xv.x * wv.x + xv.y * wv.y + xv.z * wv.z + xv.w * wv.w;
        #pragma unroll
        for (int o = 16; o; o >>= 1) d += __shfl_down_sync(0xffffffffu, d, o);
        if (lane == 0) {
            const float sc = d + b;
            g_scores[n] = sc;
            if (sc > lmax) lmax = sc;
        }
    }
    __shared__ float sm[8];
    lmax = __shfl_sync(0xffffffffu, lmax, 0);
    if (lane == 0) sm[w] = lmax;
    __syncthreads();
    if (threadIdx.x == 0) {
        float m = sm[0];
        for (int i = 1; i < nw; i++) m = fmaxf(m, sm[i]);
        atomicMax(&g_maxbits, enc_ordered(m));
    }
}

// ---------------- sum of exp ----------------
__global__ void sum_kernel() {
    const float maxf = dec_ordered(g_maxbits);
    float s = 0.f;
    for (int n = blockIdx.x * blockDim.x + threadIdx.x; n < NN;
         n += gridDim.x * blockDim.x)
        s += expf(g_scores[n] - maxf);
    #pragma unroll
    for (int o = 16; o; o >>= 1) s += __shfl_down_sync(0xffffffffu, s, o);
    __shared__ float sm[8];
    const int lane = threadIdx.x & 31, w = threadIdx.x >> 5;
    if (lane == 0) sm[w] = s;
    __syncthreads();
    if (threadIdx.x == 0) {
        float t = 0.f;
        const int nw = blockDim.x >> 5;
        for (int i = 0; i < nw; i++) t += sm[i];
        atomicAdd(&g_sum, t);
    }
}

// ---------------- normalize ----------------
__global__ void finalize_kernel(float* __restrict__ out) {
    const float maxf = dec_ordered(g_maxbits);
    const float inv = 1.0f / g_sum;
    const int n = blockIdx.x * blockDim.x + threadIdx.x;
    if (n < NN) out[n] = expf(g_scores[n] - maxf) * inv;
}

// ---------------- launch ----------------
extern "C" void kernel_launch(void* const* d_in, const int* in_sizes, int n_in,
                              void* d_out, int out_size) {
    const float* NF = (const float*)d_in[0];
    const float* EF = (const float*)d_in[1];
    const float* Wn = (const float*)d_in[2];
    const float* bn = (const float*)d_in[3];
    const float* We = (const float*)d_in[4];
    const float* be = (const float*)d_in[5];
    const float* W1 = (const float*)d_in[6];
    const float* b1 = (const float*)d_in[7];
    const float* W2 = (const float*)d_in[8];
    const float* b2 = (const float*)d_in[9];
    const float* Wo = (const float*)d_in[10];
    const float* bo = (const float*)d_in[11];
    const void*  EI = d_in[12];
    float* out = (float*)d_out;

    float *px0, *px1, *pmx, *pme;
    cudaGetSymbolAddress((void**)&px0, g_x0);
    cudaGetSymbolAddress((void**)&px1, g_x1);
    cudaGetSymbolAddress((void**)&pmx, g_mx);
    cudaGetSymbolAddress((void**)&pme, g_me);

    const int SMEM_128 = (128 * 128 + 128 * XSTR) * 4;   // ~99 KB
    const int SMEM_256 = (256 * 128 + 256 * XSTR) * 4;   // ~198 KB
    cudaFuncSetAttribute(proj_kernel<128, false>,
                         cudaFuncAttributeMaxDynamicSharedMemorySize, SMEM_128);
    cudaFuncSetAttribute(proj_kernel<256, true>,
                         cudaFuncAttributeMaxDynamicSharedMemorySize, SMEM_256);

    const int nTilesN = (NN + 63) / 64;   // 782
    const int nTilesE = EE / 64;          // 12500

    // edge index normalization + cnt zeroing
    convert_edges<<<512, 256>>>(EI);
    // zero m_e + softmax scalars
    zero_me<<<2048, 256>>>();
    // CSR build (topology computed once, reused by both conv layers)
    hist_kernel<<<512, 256>>>();
    scan_reduce<<<NB_SCAN, 256>>>();
    scan_partials<<<1, 256>>>();
    scan_final<<<NB_SCAN, 256>>>();
    fill_kernel<<<512, 256>>>();
    // x0 = relu(NF @ Wn + bn)
    proj_kernel<128, false><<<nTilesN, 256, SMEM_128>>>(NF, nullptr, Wn, bn, px0, NN);
    // m_e = segment_sum(relu(EF @ We + be), dst)   [computed once]
    edge_proj_kernel<<<nTilesE, 256>>>(EF, We, be);
    // layer 1
    gather_csr<<<1184, 256>>>(px0);
    proj_kernel<256, true><<<nTilesN, 256, SMEM_256>>>(pmx, pme, W1, b1, px1, NN);
    // layer 2
    gather_csr<<<1184, 256>>>(px1);
    proj_kernel<256, true><<<nTilesN, 256, SMEM_256>>>(pmx, pme, W2, b2, px0, NN);
    // scores + softmax
    scores_kernel<<<512, 128>>>(px0, Wo, bo);
    sum_kernel<<<512, 256>>>();
    finalize_kernel<<<(NN + 255) / 256, 256>>>(out);
}